// round 3
// baseline (speedup 1.0000x reference)
#include <cuda_runtime.h>
#include <cuda_bf16.h>
#include <stdint.h>

#define Bb 4
#define Nn 2048
#define Mm 2048
#define Cc 512
#define Hh 8
#define DHd 64
#define LOG2E 1.4426950408889634f

// ---------------- static scratch (no allocations allowed) ----------------
__device__ __nv_bfloat16 g_qhi[Bb*Hh*Nn*DHd];   // [bh][n][dh], pre-scaled by 1/8
__device__ __nv_bfloat16 g_qlo[Bb*Hh*Nn*DHd];
__device__ __nv_bfloat16 g_khi[Bb*Hh*Mm*DHd];   // [bh][m][dh], pre-scaled by kw*log2e
__device__ __nv_bfloat16 g_klo[Bb*Hh*Mm*DHd];
__device__ __nv_bfloat16 g_vhi[Bb*Hh*DHd*Mm];   // TRANSPOSED: [bh][dh][m]
__device__ __nv_bfloat16 g_vlo[Bb*Hh*DHd*Mm];
__device__ float        g_rs2[2][Bb*Hh*Nn];     // partial rowsums per m-split

// ---------------- helpers ----------------
__device__ __forceinline__ void mma_bf16(float c[4], const uint32_t a[4], const uint32_t b[2]) {
    asm volatile(
        "mma.sync.aligned.m16n8k16.row.col.f32.bf16.bf16.f32 "
        "{%0,%1,%2,%3}, {%4,%5,%6,%7}, {%8,%9}, {%0,%1,%2,%3};\n"
        : "+f"(c[0]), "+f"(c[1]), "+f"(c[2]), "+f"(c[3])
        : "r"(a[0]), "r"(a[1]), "r"(a[2]), "r"(a[3]), "r"(b[0]), "r"(b[1]));
}

__device__ __forceinline__ void split2(float x, __nv_bfloat16 &hi, __nv_bfloat16 &lo) {
    hi = __float2bfloat16_rn(x);
    lo = __float2bfloat16_rn(x - __bfloat162float(hi));
}

__device__ __forceinline__ uint32_t pk2(__nv_bfloat16 a, __nv_bfloat16 b) {
    return (uint32_t)__bfloat16_as_ushort(a) | ((uint32_t)__bfloat16_as_ushort(b) << 16);
}

// ---------------- K1: fused projections (X@W + b), bf16-split mma ----------------
// grid: (64, 8, 3)  block: 256
__global__ __launch_bounds__(256) void proj_kernel(
    const float* __restrict__ xq, const float* __restrict__ xk, const float* __restrict__ xv,
    const float* __restrict__ Wq, const float* __restrict__ bq,
    const float* __restrict__ Wk, const float* __restrict__ bk,
    const float* __restrict__ Wv, const float* __restrict__ bv,
    const float* __restrict__ kw)
{
    const float* X; const float* W; const float* bias;
    __nv_bfloat16 *Ohi, *Olo;
    int z = blockIdx.z;
    if (z == 0)      { X = xq; W = Wq; bias = bq; Ohi = g_qhi; Olo = g_qlo; }
    else if (z == 1) { X = xk; W = Wk; bias = bk; Ohi = g_khi; Olo = g_klo; }
    else             { X = xv; W = Wv; bias = bv; Ohi = g_vhi; Olo = g_vlo; }

    __shared__ __nv_bfloat16 Ahi[128][40], Alo[128][40];   // [row][k], k-chunk 32, pad 8
    __shared__ __nv_bfloat16 Bshi[64][40], Bslo[64][40];   // [col][k] transposed

    int tid = threadIdx.x, lane = tid & 31, warp = tid >> 5;
    int row0 = blockIdx.x * 128;
    int col0 = blockIdx.y * 64;
    int wr = (warp >> 1) * 32, wc = (warp & 1) * 32;
    int qr = lane >> 2, qc2 = (lane & 3) * 2;

    float acc[2][4][4];
#pragma unroll
    for (int m = 0; m < 2; m++)
#pragma unroll
        for (int n = 0; n < 4; n++)
#pragma unroll
            for (int e = 0; e < 4; e++) acc[m][n][e] = 0.0f;

    for (int kc = 0; kc < Cc; kc += 32) {
        // load A chunk 128x32 (vectorized hi/lo STS.64)
#pragma unroll
        for (int i = tid; i < 128*8; i += 256) {
            int r = i >> 3, c4 = (i & 7) * 4;
            float4 v = *(const float4*)&X[(size_t)(row0 + r)*Cc + kc + c4];
            __nv_bfloat16 h0,l0,h1,l1,h2,l2,h3,l3;
            split2(v.x, h0, l0); split2(v.y, h1, l1);
            split2(v.z, h2, l2); split2(v.w, h3, l3);
            uint2 th; th.x = pk2(h0,h1); th.y = pk2(h2,h3);
            uint2 tl; tl.x = pk2(l0,l1); tl.y = pk2(l2,l3);
            *(uint2*)&Ahi[r][c4] = th;
            *(uint2*)&Alo[r][c4] = tl;
        }
        // load B chunk 32x64: coalesced column reads, vectorized transposed stores
#pragma unroll
        for (int it = 0; it < 2; it++) {
            int slot = tid + it*256;            // 0..511
            int col = slot & 63, kk0 = (slot >> 6) * 4;
            __nv_bfloat16 h0,l0,h1,l1,h2,l2,h3,l3;
            float v0 = W[(size_t)(kc+kk0+0)*Cc + col0 + col];
            float v1 = W[(size_t)(kc+kk0+1)*Cc + col0 + col];
            float v2 = W[(size_t)(kc+kk0+2)*Cc + col0 + col];
            float v3 = W[(size_t)(kc+kk0+3)*Cc + col0 + col];
            split2(v0, h0, l0); split2(v1, h1, l1);
            split2(v2, h2, l2); split2(v3, h3, l3);
            uint2 th; th.x = pk2(h0,h1); th.y = pk2(h2,h3);
            uint2 tl; tl.x = pk2(l0,l1); tl.y = pk2(l2,l3);
            *(uint2*)&Bshi[col][kk0] = th;
            *(uint2*)&Bslo[col][kk0] = tl;
        }
        __syncthreads();
#pragma unroll
        for (int ks = 0; ks < 2; ks++) {
            int kb = ks*16 + qc2;
            uint32_t a_hi[2][4], a_lo[2][4];
#pragma unroll
            for (int m = 0; m < 2; m++) {
                int r = wr + m*16 + qr;
                a_hi[m][0] = *(const uint32_t*)&Ahi[r][kb];
                a_hi[m][1] = *(const uint32_t*)&Ahi[r+8][kb];
                a_hi[m][2] = *(const uint32_t*)&Ahi[r][kb+8];
                a_hi[m][3] = *(const uint32_t*)&Ahi[r+8][kb+8];
                a_lo[m][0] = *(const uint32_t*)&Alo[r][kb];
                a_lo[m][1] = *(const uint32_t*)&Alo[r+8][kb];
                a_lo[m][2] = *(const uint32_t*)&Alo[r][kb+8];
                a_lo[m][3] = *(const uint32_t*)&Alo[r+8][kb+8];
            }
#pragma unroll
            for (int nf = 0; nf < 4; nf++) {
                int cn = wc + nf*8 + qr;
                uint32_t b_hi[2], b_lo[2];
                b_hi[0] = *(const uint32_t*)&Bshi[cn][kb];
                b_hi[1] = *(const uint32_t*)&Bshi[cn][kb+8];
                b_lo[0] = *(const uint32_t*)&Bslo[cn][kb];
                b_lo[1] = *(const uint32_t*)&Bslo[cn][kb+8];
#pragma unroll
                for (int m = 0; m < 2; m++) {
                    mma_bf16(acc[m][nf], a_hi[m], b_hi);
                    mma_bf16(acc[m][nf], a_hi[m], b_lo);
                    mma_bf16(acc[m][nf], a_lo[m], b_hi);
                }
            }
        }
        __syncthreads();
    }

    // epilogue: + bias, * rowscale, split hi/lo, store (V transposed)
    int h = blockIdx.y;
#pragma unroll
    for (int m = 0; m < 2; m++) {
#pragma unroll
        for (int e = 0; e < 2; e++) {
            int rg = row0 + wr + m*16 + qr + e*8;
            int bb = rg >> 11, sq = rg & 2047;
            float rsc;
            if (z == 0)      rsc = 0.125f;
            else if (z == 1) rsc = kw[bb*Mm + sq] * LOG2E;
            else             rsc = 1.0f;
#pragma unroll
            for (int nf = 0; nf < 4; nf++) {
                int d = wc + nf*8 + qc2;
                float v0 = (acc[m][nf][e*2+0] + bias[col0+d])   * rsc;
                float v1 = (acc[m][nf][e*2+1] + bias[col0+d+1]) * rsc;
                __nv_bfloat16 h0, l0, h1, l1;
                split2(v0, h0, l0); split2(v1, h1, l1);
                if (z != 2) {
                    size_t o = ((size_t)((bb*Hh + h)*2048 + sq))*64 + d;
                    __nv_bfloat162 th; th.x = h0; th.y = h1;
                    __nv_bfloat162 tl; tl.x = l0; tl.y = l1;
                    *(__nv_bfloat162*)&Ohi[o] = th;
                    *(__nv_bfloat162*)&Olo[o] = tl;
                } else {
                    // transposed: [bh][dh][m]
                    size_t o = ((size_t)((bb*Hh + h)*64 + d))*2048 + sq;
                    Ohi[o] = h0; Ohi[o + 2048] = h1;
                    Olo[o] = l0; Olo[o + 2048] = l1;
                }
            }
        }
    }
}

// ---------------- K2: scores + exp + rowsum (heads looped inside CTA) ----------------
// grid: (m-split 2, n-blocks 32, b 4)  block 256
__global__ __launch_bounds__(256) void scores_kernel(
    const int* __restrict__ kmask, const float* __restrict__ af,
    const int* __restrict__ amask, float* __restrict__ out_attn)
{
    __shared__ __nv_bfloat16 Qh[64][72], Ql[64][72];
    __shared__ __nv_bfloat16 Kh[64][72], Kl[64][72];
    __shared__ float s_rs[2][64];

    int tid = threadIdx.x, lane = tid & 31, warp = tid >> 5;
    int qr = lane >> 2, qc2 = (lane & 3) * 2;
    int b = blockIdx.z;
    int n0 = blockIdx.y * 64;
    int ms = blockIdx.x;
    int mbase = ms * 1024;
    int wr = (warp & 3) * 16;       // warp row group (local)
    int wm = (warp >> 2) * 32;      // warp m-half within 64-chunk
    int n_lo = n0 + wr + qr;        // global n of this lane's low rows

    for (int h = 0; h < Hh; h++) {
        int bh = b*Hh + h;
        __syncthreads();
        {   // stage Q (64 rows x 64 dh, hi/lo)
            const __nv_bfloat16* qh = g_qhi + ((size_t)bh*Nn + n0)*64;
            const __nv_bfloat16* ql = g_qlo + ((size_t)bh*Nn + n0)*64;
#pragma unroll
            for (int i = tid; i < 64*16; i += 256) {
                int r = i >> 4, c4 = (i & 15) * 4;
                *(uint2*)&Qh[r][c4] = *(const uint2*)&qh[(size_t)r*64 + c4];
                *(uint2*)&Ql[r][c4] = *(const uint2*)&ql[(size_t)r*64 + c4];
            }
        }
        __syncthreads();
        uint32_t q_hi[4][4], q_lo[4][4];
#pragma unroll
        for (int ks = 0; ks < 4; ks++) {
            int kb = ks*16 + qc2;
            q_hi[ks][0] = *(const uint32_t*)&Qh[wr+qr][kb];
            q_hi[ks][1] = *(const uint32_t*)&Qh[wr+qr+8][kb];
            q_hi[ks][2] = *(const uint32_t*)&Qh[wr+qr][kb+8];
            q_hi[ks][3] = *(const uint32_t*)&Qh[wr+qr+8][kb+8];
            q_lo[ks][0] = *(const uint32_t*)&Ql[wr+qr][kb];
            q_lo[ks][1] = *(const uint32_t*)&Ql[wr+qr+8][kb];
            q_lo[ks][2] = *(const uint32_t*)&Ql[wr+qr][kb+8];
            q_lo[ks][3] = *(const uint32_t*)&Ql[wr+qr+8][kb+8];
        }
        float rs0 = 0.0f, rs1 = 0.0f;

        for (int mc = 0; mc < 16; mc++) {
            int m0 = mbase + mc*64;
            __syncthreads();
            {   // stage K chunk (64 m x 64 dh, hi/lo)
                const __nv_bfloat16* kh = g_khi + ((size_t)bh*Mm + m0)*64;
                const __nv_bfloat16* kl = g_klo + ((size_t)bh*Mm + m0)*64;
#pragma unroll
                for (int i = tid; i < 64*16; i += 256) {
                    int r = i >> 4, c4 = (i & 15) * 4;
                    *(uint2*)&Kh[r][c4] = *(const uint2*)&kh[(size_t)r*64 + c4];
                    *(uint2*)&Kl[r][c4] = *(const uint2*)&kl[(size_t)r*64 + c4];
                }
            }
            __syncthreads();

            float sc[4][4];
#pragma unroll
            for (int nf = 0; nf < 4; nf++)
#pragma unroll
                for (int e = 0; e < 4; e++) sc[nf][e] = 0.0f;
#pragma unroll
            for (int ks = 0; ks < 4; ks++) {
                int kb = ks*16 + qc2;
#pragma unroll
                for (int nf = 0; nf < 4; nf++) {
                    int mcol = wm + nf*8 + qr;
                    uint32_t bhh[2], bll[2];
                    bhh[0] = *(const uint32_t*)&Kh[mcol][kb];
                    bhh[1] = *(const uint32_t*)&Kh[mcol][kb+8];
                    bll[0] = *(const uint32_t*)&Kl[mcol][kb];
                    bll[1] = *(const uint32_t*)&Kl[mcol][kb+8];
                    mma_bf16(sc[nf], q_hi[ks], bhh);
                    mma_bf16(sc[nf], q_hi[ks], bll);
                    mma_bf16(sc[nf], q_lo[ks], bhh);
                }
            }

            // epilogue: p = mask ? 0 : 2^(s*af)   (kw, 1/8, log2e folded into K/Q)
            size_t af_lo = ((size_t)b*Nn + n_lo)*Mm + m0 + wm;
            size_t af_hi = af_lo + (size_t)8*Mm;
            size_t at_lo = ((size_t)bh*Nn + n_lo)*Mm + m0 + wm;
            size_t at_hi = at_lo + (size_t)8*Mm;
            const int* kmrow = kmask + b*Mm + m0 + wm;
#pragma unroll
            for (int nf = 0; nf < 4; nf++) {
                int ml = nf*8 + qc2;
                float2 afl = *(const float2*)&af[af_lo + ml];
                float2 afh = *(const float2*)&af[af_hi + ml];
                int2 aml = *(const int2*)&amask[af_lo + ml];
                int2 amh = *(const int2*)&amask[af_hi + ml];
                int2 km  = *(const int2*)&kmrow[ml];
                float p0 = (km.x | aml.x) ? 0.0f : exp2f(sc[nf][0] * afl.x);
                float p1 = (km.y | aml.y) ? 0.0f : exp2f(sc[nf][1] * afl.y);
                float p2 = (km.x | amh.x) ? 0.0f : exp2f(sc[nf][2] * afh.x);
                float p3 = (km.y | amh.y) ? 0.0f : exp2f(sc[nf][3] * afh.y);
                rs0 += p0 + p1;
                rs1 += p2 + p3;
                *(float2*)&out_attn[at_lo + ml] = make_float2(p0, p1);
                *(float2*)&out_attn[at_hi + ml] = make_float2(p2, p3);
            }
        }

        // reduce rowsums across quad lanes, combine m-halves via smem, store partial
        rs0 += __shfl_xor_sync(0xffffffffu, rs0, 1);
        rs0 += __shfl_xor_sync(0xffffffffu, rs0, 2);
        rs1 += __shfl_xor_sync(0xffffffffu, rs1, 1);
        rs1 += __shfl_xor_sync(0xffffffffu, rs1, 2);
        if ((lane & 3) == 0) {
            s_rs[wm >> 5][wr + qr]     = rs0;
            s_rs[wm >> 5][wr + qr + 8] = rs1;
        }
        __syncthreads();
        if (tid < 64)
            g_rs2[ms][(size_t)bh*Nn + n0 + tid] = s_rs[0][tid] + s_rs[1][tid];
    }
}

// ---------------- K3: normalize attn in place + AV ----------------
// grid: (n-blocks 16, bh 32)  block 256
__global__ __launch_bounds__(256) void av_kernel(
    float* __restrict__ out_hidden, float* __restrict__ out_attn)
{
    __shared__ __nv_bfloat16 Vth[64][72], Vtl[64][72];  // [dh][m-chunk]

    int tid = threadIdx.x, lane = tid & 31, warp = tid >> 5;
    int qr = lane >> 2, qc2 = (lane & 3) * 2;
    int bh = blockIdx.y, b = bh >> 3, h = bh & 7;
    int n0 = blockIdx.x * 128;
    int wrow = warp * 16;
    int n_lo = n0 + wrow + qr;

    float inv_lo = 1.0f / (g_rs2[0][(size_t)bh*Nn + n_lo]     + g_rs2[1][(size_t)bh*Nn + n_lo]);
    float inv_hi = 1.0f / (g_rs2[0][(size_t)bh*Nn + n_lo + 8] + g_rs2[1][(size_t)bh*Nn + n_lo + 8]);

    float hid[8][4];
#pragma unroll
    for (int nf = 0; nf < 8; nf++)
#pragma unroll
        for (int e = 0; e < 4; e++) hid[nf][e] = 0.0f;

    size_t at_lo = ((size_t)bh*Nn + n_lo)*Mm;
    size_t at_hi = at_lo + (size_t)8*Mm;
    const __nv_bfloat16* vh = g_vhi + (size_t)bh*64*Mm;
    const __nv_bfloat16* vl = g_vlo + (size_t)bh*64*Mm;

    for (int m0 = 0; m0 < Mm; m0 += 64) {
        __syncthreads();
#pragma unroll
        for (int i = tid; i < 64*16; i += 256) {
            int d = i >> 4, c4 = (i & 15) * 4;
            *(uint2*)&Vth[d][c4] = *(const uint2*)&vh[(size_t)d*Mm + m0 + c4];
            *(uint2*)&Vtl[d][c4] = *(const uint2*)&vl[(size_t)d*Mm + m0 + c4];
        }
        __syncthreads();

        // read p, normalize, write back, build A fragments
        uint32_t pa_hi[4][4], pa_lo[4][4];
#pragma unroll
        for (int kf = 0; kf < 4; kf++) {
            int ml = m0 + kf*16;
            float2 v0 = *(float2*)&out_attn[at_lo + ml + qc2];
            float2 v1 = *(float2*)&out_attn[at_hi + ml + qc2];
            float2 v2 = *(float2*)&out_attn[at_lo + ml + 8 + qc2];
            float2 v3 = *(float2*)&out_attn[at_hi + ml + 8 + qc2];
            v0.x *= inv_lo; v0.y *= inv_lo; v2.x *= inv_lo; v2.y *= inv_lo;
            v1.x *= inv_hi; v1.y *= inv_hi; v3.x *= inv_hi; v3.y *= inv_hi;
            *(float2*)&out_attn[at_lo + ml + qc2]     = v0;
            *(float2*)&out_attn[at_hi + ml + qc2]     = v1;
            *(float2*)&out_attn[at_lo + ml + 8 + qc2] = v2;
            *(float2*)&out_attn[at_hi + ml + 8 + qc2] = v3;
            __nv_bfloat16 h0,l0,h1,l1;
            split2(v0.x, h0, l0); split2(v0.y, h1, l1);
            pa_hi[kf][0] = pk2(h0, h1); pa_lo[kf][0] = pk2(l0, l1);
            split2(v1.x, h0, l0); split2(v1.y, h1, l1);
            pa_hi[kf][1] = pk2(h0, h1); pa_lo[kf][1] = pk2(l0, l1);
            split2(v2.x, h0, l0); split2(v2.y, h1, l1);
            pa_hi[kf][2] = pk2(h0, h1); pa_lo[kf][2] = pk2(l0, l1);
            split2(v3.x, h0, l0); split2(v3.y, h1, l1);
            pa_hi[kf][3] = pk2(h0, h1); pa_lo[kf][3] = pk2(l0, l1);
        }

        // hidden += p @ V (3-way split), V from transposed smem
#pragma unroll
        for (int ks = 0; ks < 4; ks++) {
            int mr = ks*16 + qc2;
#pragma unroll
            for (int nf = 0; nf < 8; nf++) {
                int dc = nf*8 + qr;
                uint32_t bhh[2], bll[2];
                bhh[0] = *(const uint32_t*)&Vth[dc][mr];
                bhh[1] = *(const uint32_t*)&Vth[dc][mr+8];
                bll[0] = *(const uint32_t*)&Vtl[dc][mr];
                bll[1] = *(const uint32_t*)&Vtl[dc][mr+8];
                mma_bf16(hid[nf], pa_hi[ks], bhh);
                mma_bf16(hid[nf], pa_hi[ks], bll);
                mma_bf16(hid[nf], pa_lo[ks], bhh);
            }
        }
    }

    // hidden already normalized (p was normalized before MMA)
#pragma unroll
    for (int nf = 0; nf < 8; nf++) {
        int d = nf*8 + qc2;
        size_t o_lo = ((size_t)b*Nn + n_lo)*Cc + h*64 + d;
        size_t o_hi = o_lo + (size_t)8*Cc;
        *(float2*)&out_hidden[o_lo] = make_float2(hid[nf][0], hid[nf][1]);
        *(float2*)&out_hidden[o_hi] = make_float2(hid[nf][2], hid[nf][3]);
    }
}

// ---------------- launch ----------------
extern "C" void kernel_launch(void* const* d_in, const int* in_sizes, int n_in,
                              void* d_out, int out_size) {
    const float* xq    = (const float*)d_in[0];
    const float* xk    = (const float*)d_in[1];
    const float* xv    = (const float*)d_in[2];
    const float* kw    = (const float*)d_in[3];
    const int*   kmask = (const int*)d_in[4];
    const float* af    = (const float*)d_in[5];
    const int*   amask = (const int*)d_in[6];
    const float* Wq    = (const float*)d_in[7];
    const float* bq    = (const float*)d_in[8];
    const float* Wk    = (const float*)d_in[9];
    const float* bk    = (const float*)d_in[10];
    const float* Wv    = (const float*)d_in[11];
    const float* bv    = (const float*)d_in[12];

    float* out_hidden = (float*)d_out;
    float* out_attn   = out_hidden + (size_t)Bb*Nn*Cc;

    proj_kernel<<<dim3(64, 8, 3), 256>>>(xq, xk, xv, Wq, bq, Wk, bk, Wv, bv, kw);
    scores_kernel<<<dim3(2, 32, 4), 256>>>(kmask, af, amask, out_attn);
    av_kernel<<<dim3(16, 32), 256>>>(out_hidden, out_attn);
}

// round 4
// speedup vs baseline: 1.1725x; 1.1725x over previous
#include <cuda_runtime.h>
#include <cuda_bf16.h>
#include <stdint.h>

#define Bb 4
#define Nn 2048
#define Mm 2048
#define Cc 512
#define Hh 8
#define DHd 64
#define LOG2E 1.4426950408889634f

// ---------------- static scratch (no allocations allowed) ----------------
__device__ __nv_bfloat16 g_qhi[Bb*Hh*Nn*DHd];   // [bh][n][dh], pre-scaled by 1/8
__device__ __nv_bfloat16 g_qlo[Bb*Hh*Nn*DHd];
__device__ __nv_bfloat16 g_khi[Bb*Hh*Mm*DHd];   // [bh][m][dh], pre-scaled by kw*log2e
__device__ __nv_bfloat16 g_klo[Bb*Hh*Mm*DHd];
__device__ __nv_bfloat16 g_vhi[Bb*Hh*DHd*Mm];   // TRANSPOSED: [bh][dh][m]
__device__ __nv_bfloat16 g_vlo[Bb*Hh*DHd*Mm];
__device__ float        g_inv[Bb*Hh*Nn];        // 1/rowsum

// ---------------- helpers ----------------
__device__ __forceinline__ void mma_bf16(float c[4], const uint32_t a[4], const uint32_t b[2]) {
    asm volatile(
        "mma.sync.aligned.m16n8k16.row.col.f32.bf16.bf16.f32 "
        "{%0,%1,%2,%3}, {%4,%5,%6,%7}, {%8,%9}, {%0,%1,%2,%3};\n"
        : "+f"(c[0]), "+f"(c[1]), "+f"(c[2]), "+f"(c[3])
        : "r"(a[0]), "r"(a[1]), "r"(a[2]), "r"(a[3]), "r"(b[0]), "r"(b[1]));
}

__device__ __forceinline__ void split2(float x, __nv_bfloat16 &hi, __nv_bfloat16 &lo) {
    hi = __float2bfloat16_rn(x);
    lo = __float2bfloat16_rn(x - __bfloat162float(hi));
}

__device__ __forceinline__ uint32_t pk2(__nv_bfloat16 a, __nv_bfloat16 b) {
    return (uint32_t)__bfloat16_as_ushort(a) | ((uint32_t)__bfloat16_as_ushort(b) << 16);
}

// ---------------- K1: fused projections (X@W + b), bf16-split mma ----------------
// grid: (64, 8, 3)  block: 256
__global__ __launch_bounds__(256) void proj_kernel(
    const float* __restrict__ xq, const float* __restrict__ xk, const float* __restrict__ xv,
    const float* __restrict__ Wq, const float* __restrict__ bq,
    const float* __restrict__ Wk, const float* __restrict__ bk,
    const float* __restrict__ Wv, const float* __restrict__ bv,
    const float* __restrict__ kw)
{
    const float* X; const float* W; const float* bias;
    __nv_bfloat16 *Ohi, *Olo;
    int z = blockIdx.z;
    if (z == 0)      { X = xq; W = Wq; bias = bq; Ohi = g_qhi; Olo = g_qlo; }
    else if (z == 1) { X = xk; W = Wk; bias = bk; Ohi = g_khi; Olo = g_klo; }
    else             { X = xv; W = Wv; bias = bv; Ohi = g_vhi; Olo = g_vlo; }

    __shared__ __nv_bfloat16 Ahi[128][40], Alo[128][40];   // [row][k], k-chunk 32, pad 8
    __shared__ __nv_bfloat16 Bshi[64][40], Bslo[64][40];   // [col][k] transposed

    int tid = threadIdx.x, lane = tid & 31, warp = tid >> 5;
    int row0 = blockIdx.x * 128;
    int col0 = blockIdx.y * 64;
    int wr = (warp >> 1) * 32, wc = (warp & 1) * 32;
    int qr = lane >> 2, qc2 = (lane & 3) * 2;

    float acc[2][4][4];
#pragma unroll
    for (int m = 0; m < 2; m++)
#pragma unroll
        for (int n = 0; n < 4; n++)
#pragma unroll
            for (int e = 0; e < 4; e++) acc[m][n][e] = 0.0f;

    for (int kc = 0; kc < Cc; kc += 32) {
        // load A chunk 128x32 (vectorized hi/lo STS.64)
#pragma unroll
        for (int i = tid; i < 128*8; i += 256) {
            int r = i >> 3, c4 = (i & 7) * 4;
            float4 v = *(const float4*)&X[(size_t)(row0 + r)*Cc + kc + c4];
            __nv_bfloat16 h0,l0,h1,l1,h2,l2,h3,l3;
            split2(v.x, h0, l0); split2(v.y, h1, l1);
            split2(v.z, h2, l2); split2(v.w, h3, l3);
            uint2 th; th.x = pk2(h0,h1); th.y = pk2(h2,h3);
            uint2 tl; tl.x = pk2(l0,l1); tl.y = pk2(l2,l3);
            *(uint2*)&Ahi[r][c4] = th;
            *(uint2*)&Alo[r][c4] = tl;
        }
        // load B chunk 32x64: coalesced column reads, vectorized transposed stores
#pragma unroll
        for (int it = 0; it < 2; it++) {
            int slot = tid + it*256;            // 0..511
            int col = slot & 63, kk0 = (slot >> 6) * 4;
            __nv_bfloat16 h0,l0,h1,l1,h2,l2,h3,l3;
            float v0 = W[(size_t)(kc+kk0+0)*Cc + col0 + col];
            float v1 = W[(size_t)(kc+kk0+1)*Cc + col0 + col];
            float v2 = W[(size_t)(kc+kk0+2)*Cc + col0 + col];
            float v3 = W[(size_t)(kc+kk0+3)*Cc + col0 + col];
            split2(v0, h0, l0); split2(v1, h1, l1);
            split2(v2, h2, l2); split2(v3, h3, l3);
            uint2 th; th.x = pk2(h0,h1); th.y = pk2(h2,h3);
            uint2 tl; tl.x = pk2(l0,l1); tl.y = pk2(l2,l3);
            *(uint2*)&Bshi[col][kk0] = th;
            *(uint2*)&Bslo[col][kk0] = tl;
        }
        __syncthreads();
#pragma unroll
        for (int ks = 0; ks < 2; ks++) {
            int kb = ks*16 + qc2;
            uint32_t a_hi[2][4], a_lo[2][4];
#pragma unroll
            for (int m = 0; m < 2; m++) {
                int r = wr + m*16 + qr;
                a_hi[m][0] = *(const uint32_t*)&Ahi[r][kb];
                a_hi[m][1] = *(const uint32_t*)&Ahi[r+8][kb];
                a_hi[m][2] = *(const uint32_t*)&Ahi[r][kb+8];
                a_hi[m][3] = *(const uint32_t*)&Ahi[r+8][kb+8];
                a_lo[m][0] = *(const uint32_t*)&Alo[r][kb];
                a_lo[m][1] = *(const uint32_t*)&Alo[r+8][kb];
                a_lo[m][2] = *(const uint32_t*)&Alo[r][kb+8];
                a_lo[m][3] = *(const uint32_t*)&Alo[r+8][kb+8];
            }
#pragma unroll
            for (int nf = 0; nf < 4; nf++) {
                int cn = wc + nf*8 + qr;
                uint32_t b_hi[2], b_lo[2];
                b_hi[0] = *(const uint32_t*)&Bshi[cn][kb];
                b_hi[1] = *(const uint32_t*)&Bshi[cn][kb+8];
                b_lo[0] = *(const uint32_t*)&Bslo[cn][kb];
                b_lo[1] = *(const uint32_t*)&Bslo[cn][kb+8];
#pragma unroll
                for (int m = 0; m < 2; m++) {
                    mma_bf16(acc[m][nf], a_hi[m], b_hi);
                    mma_bf16(acc[m][nf], a_hi[m], b_lo);
                    mma_bf16(acc[m][nf], a_lo[m], b_hi);
                }
            }
        }
        __syncthreads();
    }

    // epilogue: + bias, * rowscale, split hi/lo, store (V transposed)
    int h = blockIdx.y;
#pragma unroll
    for (int m = 0; m < 2; m++) {
#pragma unroll
        for (int e = 0; e < 2; e++) {
            int rg = row0 + wr + m*16 + qr + e*8;
            int bb = rg >> 11, sq = rg & 2047;
            float rsc;
            if (z == 0)      rsc = 0.125f;
            else if (z == 1) rsc = kw[bb*Mm + sq] * LOG2E;
            else             rsc = 1.0f;
#pragma unroll
            for (int nf = 0; nf < 4; nf++) {
                int d = wc + nf*8 + qc2;
                float v0 = (acc[m][nf][e*2+0] + bias[col0+d])   * rsc;
                float v1 = (acc[m][nf][e*2+1] + bias[col0+d+1]) * rsc;
                __nv_bfloat16 h0, l0, h1, l1;
                split2(v0, h0, l0); split2(v1, h1, l1);
                if (z != 2) {
                    size_t o = ((size_t)((bb*Hh + h)*2048 + sq))*64 + d;
                    __nv_bfloat162 th; th.x = h0; th.y = h1;
                    __nv_bfloat162 tl; tl.x = l0; tl.y = l1;
                    *(__nv_bfloat162*)&Ohi[o] = th;
                    *(__nv_bfloat162*)&Olo[o] = tl;
                } else {
                    // transposed: [bh][dh][m]
                    size_t o = ((size_t)((bb*Hh + h)*64 + d))*2048 + sq;
                    Ohi[o] = h0; Ohi[o + 2048] = h1;
                    Olo[o] = l0; Olo[o + 2048] = l1;
                }
            }
        }
    }
}

// ---------------- K2: scores+exp+rowsum.  af read ONCE: heads looped inside m-block ----
// grid: (n-blocks 32, b 4)  block 256 (8 warps: 4 row-groups x 2 m-halves)
__global__ __launch_bounds__(256) void scores_kernel(
    const int* __restrict__ kmask, const float* __restrict__ af,
    const int* __restrict__ amask, float* __restrict__ out_attn)
{
    __shared__ float F[64][132];                        // masked ? -1 : af
    __shared__ __nv_bfloat16 Kh[64][72], Kl[64][72];
    __shared__ float s_rs[2][64];

    int tid = threadIdx.x, lane = tid & 31, warp = tid >> 5;
    int qr = lane >> 2, qc2 = (lane & 3) * 2;
    int b = blockIdx.y;
    int n0 = blockIdx.x * 64;
    int wr = (warp & 3) * 16;       // warp row group (local)
    int wm = (warp >> 2) * 32;      // warp m-half within 64-chunk
    int n_lo = n0 + wr + qr;

    float rs[8][2];
#pragma unroll
    for (int h = 0; h < 8; h++) { rs[h][0] = 0.0f; rs[h][1] = 0.0f; }

    for (int mb = 0; mb < Mm; mb += 128) {
        __syncthreads();
        // build F tile: 64 rows x 128 cols (af/amask read once; kmask L1-hot)
#pragma unroll
        for (int i = tid; i < 64*32; i += 256) {
            int r = i >> 5, c4 = (i & 31) * 4;
            size_t gi = ((size_t)(b*Nn + n0 + r))*Mm + mb + c4;
            float4 a  = *(const float4*)&af[gi];
            int4   am = *(const int4*)&amask[gi];
            int4   km = *(const int4*)&kmask[b*Mm + mb + c4];
            F[r][c4+0] = (am.x | km.x) ? -1.0f : a.x;
            F[r][c4+1] = (am.y | km.y) ? -1.0f : a.y;
            F[r][c4+2] = (am.z | km.z) ? -1.0f : a.z;
            F[r][c4+3] = (am.w | km.w) ? -1.0f : a.w;
        }
        __syncthreads();

#pragma unroll
        for (int h = 0; h < 8; h++) {
            int bh = b*Hh + h;
            // Q fragments direct from gmem (tiny, L2-hot after first m-block)
            uint32_t q_hi[4][4], q_lo[4][4];
            {
                const __nv_bfloat16* qh = g_qhi + ((size_t)bh*Nn + n_lo)*64;
                const __nv_bfloat16* ql = g_qlo + ((size_t)bh*Nn + n_lo)*64;
#pragma unroll
                for (int ks = 0; ks < 4; ks++) {
                    int kb = ks*16 + qc2;
                    q_hi[ks][0] = *(const uint32_t*)&qh[kb];
                    q_hi[ks][1] = *(const uint32_t*)&qh[8*64 + kb];
                    q_hi[ks][2] = *(const uint32_t*)&qh[kb + 8];
                    q_hi[ks][3] = *(const uint32_t*)&qh[8*64 + kb + 8];
                    q_lo[ks][0] = *(const uint32_t*)&ql[kb];
                    q_lo[ks][1] = *(const uint32_t*)&ql[8*64 + kb];
                    q_lo[ks][2] = *(const uint32_t*)&ql[kb + 8];
                    q_lo[ks][3] = *(const uint32_t*)&ql[8*64 + kb + 8];
                }
            }
#pragma unroll 1
            for (int mc = 0; mc < 2; mc++) {
                int m0 = mb + mc*64;
                __syncthreads();
                {   // stage K chunk (64 m x 64 dh, hi/lo)
                    const __nv_bfloat16* kh = g_khi + ((size_t)bh*Mm + m0)*64;
                    const __nv_bfloat16* kl = g_klo + ((size_t)bh*Mm + m0)*64;
#pragma unroll
                    for (int i = tid; i < 64*16; i += 256) {
                        int r = i >> 4, c4 = (i & 15) * 4;
                        *(uint2*)&Kh[r][c4] = *(const uint2*)&kh[(size_t)r*64 + c4];
                        *(uint2*)&Kl[r][c4] = *(const uint2*)&kl[(size_t)r*64 + c4];
                    }
                }
                __syncthreads();

                float sc[4][4];
#pragma unroll
                for (int nf = 0; nf < 4; nf++)
#pragma unroll
                    for (int e = 0; e < 4; e++) sc[nf][e] = 0.0f;
#pragma unroll
                for (int ks = 0; ks < 4; ks++) {
                    int kb = ks*16 + qc2;
#pragma unroll
                    for (int nf = 0; nf < 4; nf++) {
                        int mcol = wm + nf*8 + qr;
                        uint32_t bhh[2], bll[2];
                        bhh[0] = *(const uint32_t*)&Kh[mcol][kb];
                        bhh[1] = *(const uint32_t*)&Kh[mcol][kb+8];
                        bll[0] = *(const uint32_t*)&Kl[mcol][kb];
                        bll[1] = *(const uint32_t*)&Kl[mcol][kb+8];
                        mma_bf16(sc[nf], q_hi[ks], bhh);
                        mma_bf16(sc[nf], q_hi[ks], bll);
                        mma_bf16(sc[nf], q_lo[ks], bhh);
                    }
                }

                // epilogue: p = F<0 ? 0 : 2^(s*F);  rowsum; write unnormalized p
                int fcol = mc*64 + wm;
                size_t at_lo = ((size_t)bh*Nn + n_lo)*Mm + m0 + wm;
                size_t at_hi = at_lo + (size_t)8*Mm;
#pragma unroll
                for (int nf = 0; nf < 4; nf++) {
                    int ml = nf*8 + qc2;
                    float2 f0 = *(const float2*)&F[wr+qr][fcol+ml];
                    float2 f1 = *(const float2*)&F[wr+qr+8][fcol+ml];
                    float p0 = (f0.x < 0.0f) ? 0.0f : exp2f(sc[nf][0] * f0.x);
                    float p1 = (f0.y < 0.0f) ? 0.0f : exp2f(sc[nf][1] * f0.y);
                    float p2 = (f1.x < 0.0f) ? 0.0f : exp2f(sc[nf][2] * f1.x);
                    float p3 = (f1.y < 0.0f) ? 0.0f : exp2f(sc[nf][3] * f1.y);
                    rs[h][0] += p0 + p1;
                    rs[h][1] += p2 + p3;
                    *(float2*)&out_attn[at_lo + ml] = make_float2(p0, p1);
                    *(float2*)&out_attn[at_hi + ml] = make_float2(p2, p3);
                }
            }
        }
    }

    // finalize: per-head rowsum reduce (quad lanes + m-halves), write inverses
#pragma unroll
    for (int h = 0; h < 8; h++) {
        float r0 = rs[h][0], r1 = rs[h][1];
        r0 += __shfl_xor_sync(0xffffffffu, r0, 1);
        r0 += __shfl_xor_sync(0xffffffffu, r0, 2);
        r1 += __shfl_xor_sync(0xffffffffu, r1, 1);
        r1 += __shfl_xor_sync(0xffffffffu, r1, 2);
        __syncthreads();
        if ((lane & 3) == 0) {
            s_rs[wm >> 5][wr + qr]     = r0;
            s_rs[wm >> 5][wr + qr + 8] = r1;
        }
        __syncthreads();
        if (tid < 64)
            g_inv[(size_t)(b*Hh + h)*Nn + n0 + tid] = 1.0f / (s_rs[0][tid] + s_rs[1][tid]);
    }
}

// ---------------- K3: normalize attn in place + AV ----------------
// grid: (n-blocks 16, bh 32)  block 256
__global__ __launch_bounds__(256) void av_kernel(
    float* __restrict__ out_hidden, float* __restrict__ out_attn)
{
    __shared__ __nv_bfloat16 Vth[64][72], Vtl[64][72];  // [dh][m-chunk]

    int tid = threadIdx.x, lane = tid & 31, warp = tid >> 5;
    int qr = lane >> 2, qc2 = (lane & 3) * 2;
    int bh = blockIdx.y, b = bh >> 3, h = bh & 7;
    int n0 = blockIdx.x * 128;
    int wrow = warp * 16;
    int n_lo = n0 + wrow + qr;

    float inv_lo = g_inv[(size_t)bh*Nn + n_lo];
    float inv_hi = g_inv[(size_t)bh*Nn + n_lo + 8];

    float hid[8][4];
#pragma unroll
    for (int nf = 0; nf < 8; nf++)
#pragma unroll
        for (int e = 0; e < 4; e++) hid[nf][e] = 0.0f;

    size_t at_lo = ((size_t)bh*Nn + n_lo)*Mm;
    size_t at_hi = at_lo + (size_t)8*Mm;
    const __nv_bfloat16* vh = g_vhi + (size_t)bh*64*Mm;
    const __nv_bfloat16* vl = g_vlo + (size_t)bh*64*Mm;

    for (int m0 = 0; m0 < Mm; m0 += 64) {
        __syncthreads();
#pragma unroll
        for (int i = tid; i < 64*16; i += 256) {
            int d = i >> 4, c4 = (i & 15) * 4;
            *(uint2*)&Vth[d][c4] = *(const uint2*)&vh[(size_t)d*Mm + m0 + c4];
            *(uint2*)&Vtl[d][c4] = *(const uint2*)&vl[(size_t)d*Mm + m0 + c4];
        }
        __syncthreads();

        // read p, normalize, write back, build A fragments
        uint32_t pa_hi[4][4], pa_lo[4][4];
#pragma unroll
        for (int kf = 0; kf < 4; kf++) {
            int ml = m0 + kf*16;
            float2 v0 = *(float2*)&out_attn[at_lo + ml + qc2];
            float2 v1 = *(float2*)&out_attn[at_hi + ml + qc2];
            float2 v2 = *(float2*)&out_attn[at_lo + ml + 8 + qc2];
            float2 v3 = *(float2*)&out_attn[at_hi + ml + 8 + qc2];
            v0.x *= inv_lo; v0.y *= inv_lo; v2.x *= inv_lo; v2.y *= inv_lo;
            v1.x *= inv_hi; v1.y *= inv_hi; v3.x *= inv_hi; v3.y *= inv_hi;
            *(float2*)&out_attn[at_lo + ml + qc2]     = v0;
            *(float2*)&out_attn[at_hi + ml + qc2]     = v1;
            *(float2*)&out_attn[at_lo + ml + 8 + qc2] = v2;
            *(float2*)&out_attn[at_hi + ml + 8 + qc2] = v3;
            __nv_bfloat16 h0,l0,h1,l1;
            split2(v0.x, h0, l0); split2(v0.y, h1, l1);
            pa_hi[kf][0] = pk2(h0, h1); pa_lo[kf][0] = pk2(l0, l1);
            split2(v1.x, h0, l0); split2(v1.y, h1, l1);
            pa_hi[kf][1] = pk2(h0, h1); pa_lo[kf][1] = pk2(l0, l1);
            split2(v2.x, h0, l0); split2(v2.y, h1, l1);
            pa_hi[kf][2] = pk2(h0, h1); pa_lo[kf][2] = pk2(l0, l1);
            split2(v3.x, h0, l0); split2(v3.y, h1, l1);
            pa_hi[kf][3] = pk2(h0, h1); pa_lo[kf][3] = pk2(l0, l1);
        }

        // hidden += p @ V (3-way split), V from transposed smem
#pragma unroll
        for (int ks = 0; ks < 4; ks++) {
            int mr = ks*16 + qc2;
#pragma unroll
            for (int nf = 0; nf < 8; nf++) {
                int dc = nf*8 + qr;
                uint32_t bhh[2], bll[2];
                bhh[0] = *(const uint32_t*)&Vth[dc][mr];
                bhh[1] = *(const uint32_t*)&Vth[dc][mr+8];
                bll[0] = *(const uint32_t*)&Vtl[dc][mr];
                bll[1] = *(const uint32_t*)&Vtl[dc][mr+8];
                mma_bf16(hid[nf], pa_hi[ks], bhh);
                mma_bf16(hid[nf], pa_hi[ks], bll);
                mma_bf16(hid[nf], pa_lo[ks], bhh);
            }
        }
    }

    // hidden already normalized (p was normalized before MMA)
#pragma unroll
    for (int nf = 0; nf < 8; nf++) {
        int d = nf*8 + qc2;
        size_t o_lo = ((size_t)b*Nn + n_lo)*Cc + h*64 + d;
        size_t o_hi = o_lo + (size_t)8*Cc;
        *(float2*)&out_hidden[o_lo] = make_float2(hid[nf][0], hid[nf][1]);
        *(float2*)&out_hidden[o_hi] = make_float2(hid[nf][2], hid[nf][3]);
    }
}

// ---------------- launch ----------------
extern "C" void kernel_launch(void* const* d_in, const int* in_sizes, int n_in,
                              void* d_out, int out_size) {
    const float* xq    = (const float*)d_in[0];
    const float* xk    = (const float*)d_in[1];
    const float* xv    = (const float*)d_in[2];
    const float* kw    = (const float*)d_in[3];
    const int*   kmask = (const int*)d_in[4];
    const float* af    = (const float*)d_in[5];
    const int*   amask = (const int*)d_in[6];
    const float* Wq    = (const float*)d_in[7];
    const float* bq    = (const float*)d_in[8];
    const float* Wk    = (const float*)d_in[9];
    const float* bk    = (const float*)d_in[10];
    const float* Wv    = (const float*)d_in[11];
    const float* bv    = (const float*)d_in[12];

    float* out_hidden = (float*)d_out;
    float* out_attn   = out_hidden + (size_t)Bb*Nn*Cc;

    proj_kernel<<<dim3(64, 8, 3), 256>>>(xq, xk, xv, Wq, bq, Wk, bk, Wv, bv, kw);
    scores_kernel<<<dim3(32, 4), 256>>>(kmask, af, amask, out_attn);
    av_kernel<<<dim3(16, 32), 256>>>(out_hidden, out_attn);
}